// round 13
// baseline (speedup 1.0000x reference)
#include <cuda_runtime.h>
#include <cuda_fp16.h>
#include <math.h>
#include <stddef.h>
#include <stdint.h>

// ---------------- problem constants ----------------
#define BB 2
#define LL 2048
#define DM 1024
#define DIN 2048
#define NHH 32
#define HD 64
#define DS 64
#define DCONVK 4
#define CONV_DIM (DIN + 2*DS)        // 2176
#define DPROJ_PAD 4352
#define NBCDT 160                    // B,C,dt columns
#define MLPI 4096
#define MTOK (BB*LL)                 // 4096
#define EPSV 1e-5f
#define NCH 16
#define CL  (LL/NCH)                 // 128

// ---------------- scratch ----------------
__device__ float g_zxx  [MTOK*(size_t)DIN];    // in-proj x cols (fp32, pre-conv)
__device__ float g_bcraw[MTOK*(size_t)(2*DS)]; // in-proj B,C cols (fp32, pre-conv)
__device__ float g_bc   [MTOK*(size_t)(2*DS)]; // conv'd B,C
__device__ float g_dt [MTOK*NHH];
__device__ float g_dA [MTOK*NHH];
__device__ float g_cumdA[MTOK*NHH];
__device__ float g_h  [MTOK*(size_t)DM];
__device__ float g_S  [BB*NHH*(size_t)NCH*HD*DS];
__device__ float g_Hi [BB*NHH*(size_t)NCH*HD*DS];

__device__ __half g_y   [MTOK*(size_t)DIN];
__device__ __half g_sz  [MTOK*(size_t)DIN];
__device__ __half g_xs_h [MTOK*(size_t)DM],  g_xs_l [MTOK*(size_t)DM];
__device__ __half g_yn_h [MTOK*(size_t)DIN];
__device__ __half g_hn_h [MTOK*(size_t)DM];
__device__ __half g_act_h[MTOK*(size_t)MLPI];

__device__ __half g_win [DPROJ_PAD*(size_t)DM];
__device__ __half g_wout[DM*(size_t)DIN];
__device__ __half g_w1  [MLPI*(size_t)DM];
__device__ __half g_w2  [DM*(size_t)MLPI];

// ---------------- asm helpers ----------------
__device__ __forceinline__ uint32_t smem_u32(const void* p) {
    uint32_t a;
    asm("{ .reg .u64 t; cvta.to.shared.u64 t, %1; cvt.u32.u64 %0, t; }" : "=r"(a) : "l"(p));
    return a;
}
__device__ __forceinline__ void cp_async16(uint32_t dst, const void* src) {
    asm volatile("cp.async.ca.shared.global [%0], [%1], 16;" :: "r"(dst), "l"(src) : "memory");
}
__device__ __forceinline__ void cp_commit() {
    asm volatile("cp.async.commit_group;" ::: "memory");
}
template<int N> __device__ __forceinline__ void cp_wait() {
    asm volatile("cp.async.wait_group %0;" :: "n"(N) : "memory");
}
__device__ __forceinline__ void ldsm4(uint32_t* r, uint32_t addr) {
    asm volatile("ldmatrix.sync.aligned.m8n8.x4.shared.b16 {%0,%1,%2,%3}, [%4];"
                 : "=r"(r[0]), "=r"(r[1]), "=r"(r[2]), "=r"(r[3]) : "r"(addr));
}
__device__ __forceinline__ void ldsm2(uint32_t* r, uint32_t addr) {
    asm volatile("ldmatrix.sync.aligned.m8n8.x2.shared.b16 {%0,%1}, [%2];"
                 : "=r"(r[0]), "=r"(r[1]) : "r"(addr));
}
__device__ __forceinline__ void mma16816(float* c, const uint32_t* a, const uint32_t* b) {
    asm volatile(
        "mma.sync.aligned.m16n8k16.row.col.f32.f16.f16.f32 "
        "{%0,%1,%2,%3}, {%4,%5,%6,%7}, {%8,%9}, {%0,%1,%2,%3};"
        : "+f"(c[0]), "+f"(c[1]), "+f"(c[2]), "+f"(c[3])
        : "r"(a[0]), "r"(a[1]), "r"(a[2]), "r"(a[3]), "r"(b[0]), "r"(b[1]));
}

// ---------------- fp16 HMMA split GEMM ----------------
// OUTM: 0 = fp32 ; 2 = half ; 3 = B/C raw fp32 (cc<128, ldc=128) + dt/dA epilogue (cc>=128).
//   OUTM==3: bias param = dt_bias, res param = A_log.
#define MT 256
#define NT 128
#define KC 64
#define STG_BYTES 81920
#define GEMM_SMEM (2*STG_BYTES)

template<int HAS_BIAS, int DO_SILU, int HAS_RES, int OUTM, int NTERM>
__global__ void __launch_bounds__(512)
gemm_mma(const __half* __restrict__ Ah, const __half* __restrict__ Al,
         const __half* __restrict__ Bh,
         const float* __restrict__ bias, const float* __restrict__ res,
         float* __restrict__ Cf, __half* __restrict__ Chi,
         int M, int N, int K, int ldc)
{
    extern __shared__ char smem[];
    const uint32_t sbase = smem_u32(smem);
    const int tid = threadIdx.x;
    const int lane = tid & 31;
    const int wid = tid >> 5;
    const int row0 = blockIdx.y * MT;
    const int col0 = blockIdx.x * NT;
    const int wr0 = (wid & 3) * 64;
    const int wc0 = (wid >> 2) * 32;

    float c[4][4][4];
    #pragma unroll
    for (int m = 0; m < 4; m++)
        #pragma unroll
        for (int j = 0; j < 4; j++)
            #pragma unroll
            for (int e = 0; e < 4; e++) c[m][j][e] = 0.f;

    const int nch = K / KC;

    auto load_stage = [&](int kc) {
        const int koff = kc * KC;
        const uint32_t st = sbase + (kc & 1) * STG_BYTES;
        #pragma unroll
        for (int i = 0; i < 4; i++) {
            int ch = tid + i * 512;
            int r = ch >> 3, c16 = ch & 7;
            uint32_t soff = (uint32_t)(r * 128 + ((c16 * 16) ^ ((r & 7) << 4)));
            const size_t go = (size_t)(row0 + r) * K + koff + c16 * 8;
            cp_async16(st + soff, Ah + go);
            if (NTERM == 2) cp_async16(st + 32768 + soff, Al + go);
        }
        #pragma unroll
        for (int i = 0; i < 2; i++) {
            int ch = tid + i * 512;
            int r = ch >> 3, c16 = ch & 7;
            uint32_t soff = (uint32_t)(r * 128 + ((c16 * 16) ^ ((r & 7) << 4)));
            cp_async16(st + 65536 + soff, Bh + (size_t)(col0 + r) * K + koff + c16 * 8);
        }
        cp_commit();
    };

    load_stage(0);

    for (int kc = 0; kc < nch; kc++) {
        if (kc + 1 < nch) { load_stage(kc + 1); cp_wait<1>(); }
        else              { cp_wait<0>(); }
        __syncthreads();

        const uint32_t st = sbase + (kc & 1) * STG_BYTES;

        #pragma unroll
        for (int ks = 0; ks < 4; ks++) {
            uint32_t a[4][4], b[4][2];
            #pragma unroll
            for (int j = 0; j < 4; j++) {
                int l = lane & 15;
                int r = wc0 + j * 8 + (l & 7);
                int cb = (ks * 2 + (l >> 3)) * 16;
                ldsm2(b[j], st + 65536 + (uint32_t)(r * 128 + (cb ^ ((r & 7) << 4))));
            }
            #pragma unroll
            for (int m = 0; m < 4; m++) {
                int r = wr0 + m * 16 + (lane & 15);
                int cb = (ks * 2 + (lane >> 4)) * 16;
                ldsm4(a[m], st + r * 128 + (cb ^ ((r & 7) << 4)));
            }
            #pragma unroll
            for (int m = 0; m < 4; m++)
                #pragma unroll
                for (int j = 0; j < 4; j++)
                    mma16816(c[m][j], a[m], b[j]);
            if (NTERM == 2) {
                #pragma unroll
                for (int m = 0; m < 4; m++) {
                    int r = wr0 + m * 16 + (lane & 15);
                    int cb = (ks * 2 + (lane >> 4)) * 16;
                    ldsm4(a[m], st + 32768 + r * 128 + (cb ^ ((r & 7) << 4)));
                }
                #pragma unroll
                for (int m = 0; m < 4; m++)
                    #pragma unroll
                    for (int j = 0; j < 4; j++)
                        mma16816(c[m][j], a[m], b[j]);
            }
        }
        __syncthreads();
    }

    #pragma unroll
    for (int m = 0; m < 4; m++) {
        const int r_ = row0 + wr0 + m * 16 + (lane >> 2);
        #pragma unroll
        for (int j = 0; j < 4; j++) {
            const int c_ = col0 + wc0 + j * 8 + 2 * (lane & 3);
            #pragma unroll
            for (int e = 0; e < 4; e++) {
                const int rr = r_ + (e >> 1) * 8;
                const int cc = c_ + (e & 1);
                if (cc < N) {
                    float v = c[m][j][e];
                    if (OUTM == 3) {
                        if (cc < 2*DS) {
                            Cf[(size_t)rr * (2*DS) + cc] = v;
                        } else {
                            int hh = cc - 2*DS;
                            float xv = v + bias[hh];              // + dt_bias
                            float dtv = (xv > 20.f) ? xv : log1pf(expf(xv));
                            g_dt[rr*NHH + hh] = dtv;
                            g_dA[rr*NHH + hh] = expf(-expf(res[hh]) * dtv); // res = A_log
                        }
                    } else {
                        if (HAS_BIAS) v += bias[cc];
                        if (DO_SILU)  v = v / (1.f + expf(-v));
                        if (HAS_RES)  v += res[(size_t)rr * ldc + cc];
                        if (OUTM == 0) Cf[(size_t)rr * ldc + cc] = v;
                        else           Chi[(size_t)rr * ldc + cc] = __float2half(v);
                    }
                }
            }
        }
    }
}

// ---------------- split fp32 -> fp16 hi/lo (float4) ----------------
__global__ void split_k(const float* __restrict__ x, __half* __restrict__ h,
                        __half* __restrict__ l, int n4)
{
    int i = blockIdx.x * blockDim.x + threadIdx.x;
    if (i >= n4) return;
    float4 v = ((const float4*)x)[i];
    __half h0 = __float2half(v.x), h1 = __float2half(v.y);
    __half h2 = __float2half(v.z), h3 = __float2half(v.w);
    ((__half2*)h)[i*2]   = __halves2half2(h0, h1);
    ((__half2*)h)[i*2+1] = __halves2half2(h2, h3);
    ((__half2*)l)[i*2]   = __halves2half2(__float2half(v.x - __half2float(h0)),
                                          __float2half(v.y - __half2float(h1)));
    ((__half2*)l)[i*2+1] = __halves2half2(__float2half(v.z - __half2float(h2)),
                                          __float2half(v.w - __half2float(h3)));
}

// ---------------- transpose + convert ----------------
__global__ void trconv_k(const float* __restrict__ W, __half* __restrict__ Th,
                         int K, int N, int Npad)
{
    __shared__ float t[32][33];
    int kb = blockIdx.y * 32, nb = blockIdx.x * 32;
    int x = threadIdx.x & 31, y = threadIdx.x >> 5;
    #pragma unroll
    for (int i = y; i < 32; i += 8) {
        int kk = kb + i, nn = nb + x;
        t[i][x] = (kk < K && nn < N) ? W[(size_t)kk * N + nn] : 0.f;
    }
    __syncthreads();
    #pragma unroll
    for (int i = y; i < 32; i += 8) {
        int nn = nb + i, kk = kb + x;
        if (nn < Npad && kk < K)
            Th[(size_t)nn * K + kk] = __float2half(t[x][i]);
    }
}

// ---------------- conv for B/C channels only (+silu), 4 tokens x 4 ch ----------------
__global__ void conv_bc_k(const float* __restrict__ conv_w, const float* __restrict__ conv_b)
{
    int idx = blockIdx.x * blockDim.x + threadIdx.x;
    if (idx >= (MTOK/4) * (2*DS/4)) return;
    int cg = idx % (2*DS/4);          // 0..31
    int tg = idx / (2*DS/4);
    int g0 = tg * 4;
    int t0 = g0 % LL;
    int c  = cg * 4;                   // local B/C channel
    int cw = DIN + c;                  // conv weight channel index

    float4 w0 = ((const float4*)conv_w)[cw+0];
    float4 w1 = ((const float4*)conv_w)[cw+1];
    float4 w2 = ((const float4*)conv_w)[cw+2];
    float4 w3 = ((const float4*)conv_w)[cw+3];
    float4 bias4 = *(const float4*)(conv_b + cw);

    float4 zv[7];
    const float* base = g_bcraw + (size_t)g0 * (2*DS) + c;
    #pragma unroll
    for (int k = 0; k < 7; k++) {
        int toff = k - 3;
        if (t0 + toff >= 0)
            zv[k] = *(const float4*)(base + (long long)toff * (2*DS));
        else
            zv[k] = make_float4(0.f, 0.f, 0.f, 0.f);
    }

    #pragma unroll
    for (int j = 0; j < 4; j++) {
        float a0 = bias4.x, a1 = bias4.y, a2 = bias4.z, a3 = bias4.w;
        #pragma unroll
        for (int k = 0; k < 4; k++) {
            float4 zvv = zv[j + k];
            float wk0 = (k==0)?w0.x:(k==1)?w0.y:(k==2)?w0.z:w0.w;
            float wk1 = (k==0)?w1.x:(k==1)?w1.y:(k==2)?w1.z:w1.w;
            float wk2 = (k==0)?w2.x:(k==1)?w2.y:(k==2)?w2.z:w2.w;
            float wk3 = (k==0)?w3.x:(k==1)?w3.y:(k==2)?w3.z:w3.w;
            a0 = fmaf(zvv.x, wk0, a0);
            a1 = fmaf(zvv.y, wk1, a1);
            a2 = fmaf(zvv.z, wk2, a2);
            a3 = fmaf(zvv.w, wk3, a3);
        }
        float4 o;
        o.x = a0 / (1.f + expf(-a0));
        o.y = a1 / (1.f + expf(-a1));
        o.z = a2 / (1.f + expf(-a2));
        o.w = a3 / (1.f + expf(-a3));
        *(float4*)(g_bc + (size_t)(g0 + j) * (2*DS) + c) = o;
    }
}

// ---------------- Phase A: local scan with fused x-conv ----------------
__global__ void scan_local_k(const float* __restrict__ D_param,
                             const float* __restrict__ conv_w,
                             const float* __restrict__ conv_b)
{
    int chunk = blockIdx.x;
    int bh = blockIdx.y;
    int b = bh >> 5;
    int h = bh & 31;
    int tid = threadIdx.x;
    int p = tid >> 3;
    int n0 = (tid & 7) * 8;
    float hs[8] = {};
    float Dv = D_param[h];
    float cum = 1.f;

    const int ch = h * HD + p;                 // x channel
    float4 cwv = ((const float4*)conv_w)[ch];  // 4 taps
    float cbv = conv_b[ch];

    int ts0 = chunk * CL;                      // seq position of first token
    int tok0 = b * LL + ts0;

    // rolling window of raw x: xw[k] = zxx[token ts0-3+k]
    const float* zp = g_zxx + (size_t)tok0 * DIN + ch;
    float xw0 = (ts0 >= 3) ? zp[-3*(long long)DIN] : 0.f;
    float xw1 = (ts0 >= 2) ? zp[-2*(long long)DIN] : 0.f;
    float xw2 = (ts0 >= 1) ? zp[-1*(long long)DIN] : 0.f;
    float xw3 = zp[0];

    float dA_c = g_dA[tok0*NHH + h];
    float dt_c = g_dt[tok0*NHH + h];
    const float* bcrow = g_bc + (size_t)tok0 * (2*DS);
    float4 B1c = *(const float4*)(bcrow + n0);
    float4 B2c = *(const float4*)(bcrow + n0 + 4);
    float4 C1c = *(const float4*)(bcrow + DS + n0);
    float4 C2c = *(const float4*)(bcrow + DS + n0 + 4);

    for (int t = 0; t < CL; t++) {
        // prefetch next-step data
        float dA_n = 0.f, dt_n = 0.f, xr_n = 0.f;
        float4 B1n = {}, B2n = {}, C1n = {}, C2n = {};
        const float* bn = bcrow + 2*DS;
        if (t + 1 < CL) {
            int tokn = tok0 + t + 1;
            dA_n = g_dA[tokn*NHH + h];
            dt_n = g_dt[tokn*NHH + h];
            xr_n = zp[(size_t)(t+1) * DIN];
            B1n = *(const float4*)(bn + n0);
            B2n = *(const float4*)(bn + n0 + 4);
            C1n = *(const float4*)(bn + DS + n0);
            C2n = *(const float4*)(bn + DS + n0 + 4);
        }

        // fused depthwise conv + silu for x
        float acc = cbv;
        acc = fmaf(xw0, cwv.x, acc);
        acc = fmaf(xw1, cwv.y, acc);
        acc = fmaf(xw2, cwv.z, acc);
        acc = fmaf(xw3, cwv.w, acc);
        float xp = acc / (1.f + expf(-acc));

        cum *= dA_c;
        float dtx = dt_c * xp;
        float Bv[8] = {B1c.x,B1c.y,B1c.z,B1c.w,B2c.x,B2c.y,B2c.z,B2c.w};
        float Cv[8] = {C1c.x,C1c.y,C1c.z,C1c.w,C2c.x,C2c.y,C2c.z,C2c.w};
        float part = 0.f;
        #pragma unroll
        for (int i = 0; i < 8; i++) {
            hs[i] = fmaf(dA_c, hs[i], dtx * Bv[i]);
            part  = fmaf(hs[i], Cv[i], part);
        }
        part += __shfl_down_sync(0xffffffffu, part, 4);
        part += __shfl_down_sync(0xffffffffu, part, 2);
        part += __shfl_down_sync(0xffffffffu, part, 1);
        int tok = tok0 + t;
        if ((tid & 7) == 0)
            g_y[(size_t)tok * DIN + ch] = __float2half(part + Dv * xp);
        if (tid == 0)
            g_cumdA[tok*NHH + h] = cum;

        dA_c = dA_n; dt_c = dt_n;
        B1c = B1n; B2c = B2n; C1c = C1n; C2c = C2n;
        xw0 = xw1; xw1 = xw2; xw2 = xw3; xw3 = xr_n;
        bcrow = bn;
    }

    float* Sp = g_S + ((size_t)bh * NCH + chunk) * (HD*DS) + p * DS + n0;
    #pragma unroll
    for (int i = 0; i < 8; i++) Sp[i] = hs[i];
}

// ---------------- Phase B: combine ----------------
__global__ void scan_combine_k()
{
    int bh = blockIdx.x;
    int b = bh >> 5;
    int h = bh & 31;
    int tid = threadIdx.x;
    int p = tid >> 3;
    int n0 = (tid & 7) * 8;
    float H[8] = {};

    for (int c = 0; c < NCH; c++) {
        float* Hp = g_Hi + ((size_t)bh * NCH + c) * (HD*DS) + p * DS + n0;
        #pragma unroll
        for (int i = 0; i < 8; i++) Hp[i] = H[i];
        if (c + 1 < NCH) {
            int lastTok = b * LL + c * CL + (CL - 1);
            float Pc = g_cumdA[lastTok*NHH + h];
            const float* Sp = g_S + ((size_t)bh * NCH + c) * (HD*DS) + p * DS + n0;
            #pragma unroll
            for (int i = 0; i < 8; i++) H[i] = fmaf(Pc, H[i], Sp[i]);
        }
    }
}

// ---------------- Phase C: cross-chunk correction ----------------
__global__ void scan_correct_k()
{
    int chunk = blockIdx.x + 1;
    int bh = blockIdx.y;
    int b = bh >> 5;
    int h = bh & 31;
    int tid = threadIdx.x;
    int p = tid >> 3;
    int n0 = (tid & 7) * 8;

    float H[8];
    const float* Hp = g_Hi + ((size_t)bh * NCH + chunk) * (HD*DS) + p * DS + n0;
    #pragma unroll
    for (int i = 0; i < 8; i++) H[i] = Hp[i];

    int tok0 = b * LL + chunk * CL;
    const float* bcrow = g_bc + (size_t)tok0 * (2*DS);

    #pragma unroll 2
    for (int t = 0; t < CL; t++) {
        int tok = tok0 + t;
        float4 C1 = *(const float4*)(bcrow + DS + n0);
        float4 C2 = *(const float4*)(bcrow + DS + n0 + 4);
        float cum = g_cumdA[tok*NHH + h];
        float Cv[8] = {C1.x,C1.y,C1.z,C1.w,C2.x,C2.y,C2.z,C2.w};
        float part = 0.f;
        #pragma unroll
        for (int i = 0; i < 8; i++) part = fmaf(H[i], Cv[i], part);
        part += __shfl_down_sync(0xffffffffu, part, 4);
        part += __shfl_down_sync(0xffffffffu, part, 2);
        part += __shfl_down_sync(0xffffffffu, part, 1);
        if ((tid & 7) == 0) {
            __half* yp = g_y + (size_t)tok * DIN + h*HD + p;
            *yp = __float2half(__half2float(*yp) + cum * part);
        }
        bcrow += 2*DS;
    }
}

// ---------------- gated RMSNorm -> fp16 ----------------
__global__ void __launch_bounds__(512) gatenorm_k(const float* __restrict__ norm_w)
{
    int tok = blockIdx.x;
    int tid = threadIdx.x;
    __shared__ float red[16];

    __half2 ya = ((const __half2*)(g_y + (size_t)tok * DIN))[tid*2];
    __half2 yb = ((const __half2*)(g_y + (size_t)tok * DIN))[tid*2+1];
    __half2 z01 = ((const __half2*)(g_sz + (size_t)tok * DIN))[tid*2];
    __half2 z23 = ((const __half2*)(g_sz + (size_t)tok * DIN))[tid*2+1];
    float v0 = __half2float(ya.x) * __half2float(z01.x);
    float v1 = __half2float(ya.y) * __half2float(z01.y);
    float v2 = __half2float(yb.x) * __half2float(z23.x);
    float v3 = __half2float(yb.y) * __half2float(z23.y);
    float ss = v0*v0 + v1*v1 + v2*v2 + v3*v3;
    #pragma unroll
    for (int o = 16; o > 0; o >>= 1) ss += __shfl_xor_sync(0xffffffffu, ss, o);
    if ((tid & 31) == 0) red[tid >> 5] = ss;
    __syncthreads();
    if (tid < 32) {
        float s = (tid < 16) ? red[tid] : 0.f;
        #pragma unroll
        for (int o = 8; o > 0; o >>= 1) s += __shfl_xor_sync(0xffffffffu, s, o);
        if (tid == 0) red[0] = s;
    }
    __syncthreads();
    float scale = rsqrtf(red[0] / DIN + EPSV);
    float4 w4 = ((const float4*)norm_w)[tid];
    ((__half2*)(g_yn_h + (size_t)tok * DIN))[tid*2] =
        __halves2half2(__float2half(v0 * scale * w4.x), __float2half(v1 * scale * w4.y));
    ((__half2*)(g_yn_h + (size_t)tok * DIN))[tid*2+1] =
        __halves2half2(__float2half(v2 * scale * w4.z), __float2half(v3 * scale * w4.w));
}

// ---------------- plain RMSNorm -> fp16 ----------------
__global__ void __launch_bounds__(512) rmsnorm_k(const float* __restrict__ x,
                                                 const float* __restrict__ w)
{
    int tok = blockIdx.x;
    int tid = threadIdx.x;
    __shared__ float red[16];

    float2 v = ((const float2*)(x + (size_t)tok * DM))[tid];
    float ss = v.x*v.x + v.y*v.y;
    #pragma unroll
    for (int o = 16; o > 0; o >>= 1) ss += __shfl_xor_sync(0xffffffffu, ss, o);
    if ((tid & 31) == 0) red[tid >> 5] = ss;
    __syncthreads();
    if (tid < 32) {
        float s = (tid < 16) ? red[tid] : 0.f;
        #pragma unroll
        for (int o = 8; o > 0; o >>= 1) s += __shfl_xor_sync(0xffffffffu, s, o);
        if (tid == 0) red[0] = s;
    }
    __syncthreads();
    float scale = rsqrtf(red[0] / DM + EPSV);
    float2 w2 = ((const float2*)w)[tid];
    ((__half2*)(g_hn_h + (size_t)tok * DM))[tid] =
        __halves2half2(__float2half(v.x * scale * w2.x),
                       __float2half(v.y * scale * w2.y));
}

// ---------------- launch ----------------
extern "C" void kernel_launch(void* const* d_in, const int* in_sizes, int n_in,
                              void* d_out, int out_size)
{
    const float* x       = (const float*)d_in[0];
    const float* W_in    = (const float*)d_in[1];
    const float* conv_w  = (const float*)d_in[2];
    const float* conv_b  = (const float*)d_in[3];
    const float* dt_bias = (const float*)d_in[4];
    const float* A_log   = (const float*)d_in[5];
    const float* D_param = (const float*)d_in[6];
    const float* norm_w  = (const float*)d_in[7];
    const float* W_out   = (const float*)d_in[8];
    const float* rms_w   = (const float*)d_in[9];
    const float* mlp_w1  = (const float*)d_in[10];
    const float* mlp_b1  = (const float*)d_in[11];
    const float* mlp_w2  = (const float*)d_in[12];
    const float* mlp_b2  = (const float*)d_in[13];
    float* out           = (float*)d_out;
    (void)in_sizes; (void)n_in; (void)out_size;

    float *p_zxx, *p_bcraw, *p_h;
    __half *p_sz, *p_xs_h, *p_xs_l, *p_yn_h, *p_hn_h, *p_act_h;
    __half *p_win, *p_wout, *p_w1, *p_w2;
    cudaGetSymbolAddress((void**)&p_zxx, g_zxx);
    cudaGetSymbolAddress((void**)&p_bcraw, g_bcraw);
    cudaGetSymbolAddress((void**)&p_h, g_h);
    cudaGetSymbolAddress((void**)&p_sz, g_sz);
    cudaGetSymbolAddress((void**)&p_xs_h, g_xs_h);   cudaGetSymbolAddress((void**)&p_xs_l, g_xs_l);
    cudaGetSymbolAddress((void**)&p_yn_h, g_yn_h);
    cudaGetSymbolAddress((void**)&p_hn_h, g_hn_h);
    cudaGetSymbolAddress((void**)&p_act_h, g_act_h);
    cudaGetSymbolAddress((void**)&p_win, g_win);
    cudaGetSymbolAddress((void**)&p_wout, g_wout);
    cudaGetSymbolAddress((void**)&p_w1, g_w1);
    cudaGetSymbolAddress((void**)&p_w2, g_w2);

    cudaFuncSetAttribute(gemm_mma<0,0,0,3,2>, cudaFuncAttributeMaxDynamicSharedMemorySize, GEMM_SMEM);
    cudaFuncSetAttribute(gemm_mma<0,0,0,0,1>, cudaFuncAttributeMaxDynamicSharedMemorySize, GEMM_SMEM);
    cudaFuncSetAttribute(gemm_mma<0,1,0,2,1>, cudaFuncAttributeMaxDynamicSharedMemorySize, GEMM_SMEM);
    cudaFuncSetAttribute(gemm_mma<0,0,1,0,1>, cudaFuncAttributeMaxDynamicSharedMemorySize, GEMM_SMEM);
    cudaFuncSetAttribute(gemm_mma<1,1,0,2,1>, cudaFuncAttributeMaxDynamicSharedMemorySize, GEMM_SMEM);
    cudaFuncSetAttribute(gemm_mma<1,0,1,0,1>, cudaFuncAttributeMaxDynamicSharedMemorySize, GEMM_SMEM);

    static cudaStream_t s1 = nullptr;
    static cudaEvent_t ev0 = nullptr, evA = nullptr, evW = nullptr, evJ = nullptr;
    if (!s1) {
        cudaStreamCreateWithFlags(&s1, cudaStreamNonBlocking);
        cudaEventCreateWithFlags(&ev0, cudaEventDisableTiming);
        cudaEventCreateWithFlags(&evA, cudaEventDisableTiming);
        cudaEventCreateWithFlags(&evW, cudaEventDisableTiming);
        cudaEventCreateWithFlags(&evJ, cudaEventDisableTiming);
    }

    dim3 blk(256);

    cudaEventRecord(ev0, 0);
    cudaStreamWaitEvent(s1, ev0, 0);

    // main: activation split
    split_k<<<(MTOK*DM/4 + 255)/256, blk>>>(x, p_xs_h, p_xs_l, MTOK*DM/4);
    cudaEventRecord(evA, 0);

    // side: weight transposes, then z-GEMM
    trconv_k<<<dim3(DPROJ_PAD/32, DM/32), blk, 0, s1>>>(W_in, p_win, DM, 2*DIN + 2*DS + NHH, DPROJ_PAD);
    cudaEventRecord(evW, s1);
    trconv_k<<<dim3(DM/32, DIN/32),  blk, 0, s1>>>(W_out,  p_wout, DIN,  DM,   DM);
    trconv_k<<<dim3(MLPI/32, DM/32), blk, 0, s1>>>(mlp_w1, p_w1,   DM,   MLPI, MLPI);
    trconv_k<<<dim3(DM/32, MLPI/32), blk, 0, s1>>>(mlp_w2, p_w2,   MLPI, DM,   DM);
    cudaStreamWaitEvent(s1, evA, 0);
    gemm_mma<0,1,0,2,1><<<dim3(DIN/NT, MTOK/MT), 512, GEMM_SMEM, s1>>>(
        p_xs_h, nullptr, p_win, nullptr, nullptr,
        nullptr, p_sz, MTOK, DIN, DM, DIN);
    cudaEventRecord(evJ, s1);

    // main: in-proj
    cudaStreamWaitEvent(0, evW, 0);
    // B/C/dt columns: 2-term; B/C raw -> g_bcraw, dt/dA in epilogue
    gemm_mma<0,0,0,3,2><<<dim3((NBCDT+NT-1)/NT, MTOK/MT), 512, GEMM_SMEM>>>(
        p_xs_h, p_xs_l, p_win + (size_t)(2*DIN) * DM, dt_bias, A_log,
        p_bcraw, nullptr, MTOK, NBCDT, DM, 2*DS);
    // x columns: 1-term, fp32
    gemm_mma<0,0,0,0,1><<<dim3(DIN/NT, MTOK/MT), 512, GEMM_SMEM>>>(
        p_xs_h, nullptr, p_win + (size_t)DIN * DM, nullptr, nullptr,
        p_zxx, nullptr, MTOK, DIN, DM, DIN);

    // conv B/C only, then scan (x-conv fused)
    conv_bc_k<<<((MTOK/4)*(2*DS/4) + 255)/256, blk>>>(conv_w, conv_b);
    scan_local_k<<<dim3(NCH, BB*NHH), 512>>>(D_param, conv_w, conv_b);
    scan_combine_k<<<BB*NHH, 512>>>();
    scan_correct_k<<<dim3(NCH-1, BB*NHH), 512>>>();

    cudaStreamWaitEvent(0, evJ, 0);

    gatenorm_k<<<MTOK, 512>>>(norm_w);
    gemm_mma<0,0,1,0,1><<<dim3(DM/NT, MTOK/MT), 512, GEMM_SMEM>>>(
        p_yn_h, nullptr, p_wout, nullptr, x, p_h, nullptr,
        MTOK, DM, DIN, DM);
    rmsnorm_k<<<MTOK, 512>>>(p_h, rms_w);
    gemm_mma<1,1,0,2,1><<<dim3(MLPI/NT, MTOK/MT), 512, GEMM_SMEM>>>(
        p_hn_h, nullptr, p_w1, mlp_b1, nullptr, nullptr, p_act_h,
        MTOK, MLPI, DM, MLPI);
    gemm_mma<1,0,1,0,1><<<dim3(DM/NT, MTOK/MT), 512, GEMM_SMEM>>>(
        p_act_h, nullptr, p_w2, mlp_b2, p_h, out, nullptr,
        MTOK, DM, MLPI, DM);
}

// round 14
// speedup vs baseline: 1.1576x; 1.1576x over previous
#include <cuda_runtime.h>
#include <cuda_fp16.h>
#include <math.h>
#include <stddef.h>
#include <stdint.h>

// ---------------- problem constants ----------------
#define BB 2
#define LL 2048
#define DM 1024
#define DIN 2048
#define NHH 32
#define HD 64
#define DS 64
#define DCONVK 4
#define CONV_DIM (DIN + 2*DS)        // 2176
#define DPROJ (2*DIN + 2*DS + NHH)   // 4256
#define DPROJ_PAD 4352
#define NBCDT 160                    // B,C,dt columns
#define MLPI 4096
#define MTOK (BB*LL)                 // 4096
#define EPSV 1e-5f
#define NCH 16
#define CL  (LL/NCH)                 // 128

// ---------------- scratch ----------------
__device__ float g_zx [MTOK*(size_t)DPROJ];   // in-proj out (x/B/C cols at DIN..)
__device__ float g_bc [MTOK*(size_t)(2*DS)];  // conv'd B,C (fp32)
__device__ float g_dt [MTOK*NHH];
__device__ float g_dA [MTOK*NHH];
__device__ float g_cumdA[MTOK*NHH];
__device__ float g_h  [MTOK*(size_t)DM];
__device__ float g_S  [BB*NHH*(size_t)NCH*HD*DS];
__device__ float g_Hi [BB*NHH*(size_t)NCH*HD*DS];

__device__ __half g_xsc [MTOK*(size_t)DIN];   // conv'd x (fp16)
__device__ __half g_y   [MTOK*(size_t)DIN];   // scan output (fp16)
__device__ __half g_sz  [MTOK*(size_t)DIN];
__device__ __half g_xs_h [MTOK*(size_t)DM],  g_xs_l [MTOK*(size_t)DM];
__device__ __half g_yn_h [MTOK*(size_t)DIN];
__device__ __half g_hn_h [MTOK*(size_t)DM];
__device__ __half g_act_h[MTOK*(size_t)MLPI];

__device__ __half g_win [DPROJ_PAD*(size_t)DM];
__device__ __half g_wout[DM*(size_t)DIN];
__device__ __half g_w1  [MLPI*(size_t)DM];
__device__ __half g_w2  [DM*(size_t)MLPI];

// ---------------- asm helpers ----------------
__device__ __forceinline__ uint32_t smem_u32(const void* p) {
    uint32_t a;
    asm("{ .reg .u64 t; cvta.to.shared.u64 t, %1; cvt.u32.u64 %0, t; }" : "=r"(a) : "l"(p));
    return a;
}
__device__ __forceinline__ void cp_async16(uint32_t dst, const void* src) {
    asm volatile("cp.async.ca.shared.global [%0], [%1], 16;" :: "r"(dst), "l"(src) : "memory");
}
__device__ __forceinline__ void cp_commit() {
    asm volatile("cp.async.commit_group;" ::: "memory");
}
template<int N> __device__ __forceinline__ void cp_wait() {
    asm volatile("cp.async.wait_group %0;" :: "n"(N) : "memory");
}
__device__ __forceinline__ void ldsm4(uint32_t* r, uint32_t addr) {
    asm volatile("ldmatrix.sync.aligned.m8n8.x4.shared.b16 {%0,%1,%2,%3}, [%4];"
                 : "=r"(r[0]), "=r"(r[1]), "=r"(r[2]), "=r"(r[3]) : "r"(addr));
}
__device__ __forceinline__ void ldsm2(uint32_t* r, uint32_t addr) {
    asm volatile("ldmatrix.sync.aligned.m8n8.x2.shared.b16 {%0,%1}, [%2];"
                 : "=r"(r[0]), "=r"(r[1]) : "r"(addr));
}
__device__ __forceinline__ void mma16816(float* c, const uint32_t* a, const uint32_t* b) {
    asm volatile(
        "mma.sync.aligned.m16n8k16.row.col.f32.f16.f16.f32 "
        "{%0,%1,%2,%3}, {%4,%5,%6,%7}, {%8,%9}, {%0,%1,%2,%3};"
        : "+f"(c[0]), "+f"(c[1]), "+f"(c[2]), "+f"(c[3])
        : "r"(a[0]), "r"(a[1]), "r"(a[2]), "r"(a[3]), "r"(b[0]), "r"(b[1]));
}

// ---------------- fp16 HMMA split GEMM ----------------
// OUTM: 0 = fp32 ; 2 = half ; 3 = fp32 for cc<2*DS, dt/dA epilogue for cc>=2*DS
//   (OUTM==3: bias param = dt_bias, res param = A_log).
#define MT 256
#define NT 128
#define KC 64
#define STG_BYTES 81920
#define GEMM_SMEM (2*STG_BYTES)

template<int HAS_BIAS, int DO_SILU, int HAS_RES, int OUTM, int NTERM>
__global__ void __launch_bounds__(512)
gemm_mma(const __half* __restrict__ Ah, const __half* __restrict__ Al,
         const __half* __restrict__ Bh,
         const float* __restrict__ bias, const float* __restrict__ res,
         float* __restrict__ Cf, __half* __restrict__ Chi,
         int M, int N, int K, int ldc)
{
    extern __shared__ char smem[];
    const uint32_t sbase = smem_u32(smem);
    const int tid = threadIdx.x;
    const int lane = tid & 31;
    const int wid = tid >> 5;
    const int row0 = blockIdx.y * MT;
    const int col0 = blockIdx.x * NT;
    const int wr0 = (wid & 3) * 64;
    const int wc0 = (wid >> 2) * 32;

    float c[4][4][4];
    #pragma unroll
    for (int m = 0; m < 4; m++)
        #pragma unroll
        for (int j = 0; j < 4; j++)
            #pragma unroll
            for (int e = 0; e < 4; e++) c[m][j][e] = 0.f;

    const int nch = K / KC;

    auto load_stage = [&](int kc) {
        const int koff = kc * KC;
        const uint32_t st = sbase + (kc & 1) * STG_BYTES;
        #pragma unroll
        for (int i = 0; i < 4; i++) {
            int ch = tid + i * 512;
            int r = ch >> 3, c16 = ch & 7;
            uint32_t soff = (uint32_t)(r * 128 + ((c16 * 16) ^ ((r & 7) << 4)));
            const size_t go = (size_t)(row0 + r) * K + koff + c16 * 8;
            cp_async16(st + soff, Ah + go);
            if (NTERM == 2) cp_async16(st + 32768 + soff, Al + go);
        }
        #pragma unroll
        for (int i = 0; i < 2; i++) {
            int ch = tid + i * 512;
            int r = ch >> 3, c16 = ch & 7;
            uint32_t soff = (uint32_t)(r * 128 + ((c16 * 16) ^ ((r & 7) << 4)));
            cp_async16(st + 65536 + soff, Bh + (size_t)(col0 + r) * K + koff + c16 * 8);
        }
        cp_commit();
    };

    load_stage(0);

    for (int kc = 0; kc < nch; kc++) {
        if (kc + 1 < nch) { load_stage(kc + 1); cp_wait<1>(); }
        else              { cp_wait<0>(); }
        __syncthreads();

        const uint32_t st = sbase + (kc & 1) * STG_BYTES;

        #pragma unroll
        for (int ks = 0; ks < 4; ks++) {
            uint32_t a[4][4], b[4][2];
            #pragma unroll
            for (int j = 0; j < 4; j++) {
                int l = lane & 15;
                int r = wc0 + j * 8 + (l & 7);
                int cb = (ks * 2 + (l >> 3)) * 16;
                ldsm2(b[j], st + 65536 + (uint32_t)(r * 128 + (cb ^ ((r & 7) << 4))));
            }
            #pragma unroll
            for (int m = 0; m < 4; m++) {
                int r = wr0 + m * 16 + (lane & 15);
                int cb = (ks * 2 + (lane >> 4)) * 16;
                ldsm4(a[m], st + r * 128 + (cb ^ ((r & 7) << 4)));
            }
            #pragma unroll
            for (int m = 0; m < 4; m++)
                #pragma unroll
                for (int j = 0; j < 4; j++)
                    mma16816(c[m][j], a[m], b[j]);
            if (NTERM == 2) {
                #pragma unroll
                for (int m = 0; m < 4; m++) {
                    int r = wr0 + m * 16 + (lane & 15);
                    int cb = (ks * 2 + (lane >> 4)) * 16;
                    ldsm4(a[m], st + 32768 + r * 128 + (cb ^ ((r & 7) << 4)));
                }
                #pragma unroll
                for (int m = 0; m < 4; m++)
                    #pragma unroll
                    for (int j = 0; j < 4; j++)
                        mma16816(c[m][j], a[m], b[j]);
            }
        }
        __syncthreads();
    }

    #pragma unroll
    for (int m = 0; m < 4; m++) {
        const int r_ = row0 + wr0 + m * 16 + (lane >> 2);
        #pragma unroll
        for (int j = 0; j < 4; j++) {
            const int c_ = col0 + wc0 + j * 8 + 2 * (lane & 3);
            #pragma unroll
            for (int e = 0; e < 4; e++) {
                const int rr = r_ + (e >> 1) * 8;
                const int cc = c_ + (e & 1);
                if (cc < N) {
                    float v = c[m][j][e];
                    if (OUTM == 3) {
                        if (cc < 2*DS) {
                            Cf[(size_t)rr * ldc + cc] = v;   // raw B/C -> zx cols
                        } else {
                            int hh = cc - 2*DS;
                            float xv = v + bias[hh];          // + dt_bias
                            float dtv = (xv > 20.f) ? xv : log1pf(expf(xv));
                            g_dt[rr*NHH + hh] = dtv;
                            g_dA[rr*NHH + hh] = expf(-expf(res[hh]) * dtv); // res = A_log
                        }
                    } else {
                        if (HAS_BIAS) v += bias[cc];
                        if (DO_SILU)  v = v / (1.f + expf(-v));
                        if (HAS_RES)  v += res[(size_t)rr * ldc + cc];
                        if (OUTM == 0) Cf[(size_t)rr * ldc + cc] = v;
                        else           Chi[(size_t)rr * ldc + cc] = __float2half(v);
                    }
                }
            }
        }
    }
}

// ---------------- split fp32 -> fp16 hi/lo (float4) ----------------
__global__ void split_k(const float* __restrict__ x, __half* __restrict__ h,
                        __half* __restrict__ l, int n4)
{
    int i = blockIdx.x * blockDim.x + threadIdx.x;
    if (i >= n4) return;
    float4 v = ((const float4*)x)[i];
    __half h0 = __float2half(v.x), h1 = __float2half(v.y);
    __half h2 = __float2half(v.z), h3 = __float2half(v.w);
    ((__half2*)h)[i*2]   = __halves2half2(h0, h1);
    ((__half2*)h)[i*2+1] = __halves2half2(h2, h3);
    ((__half2*)l)[i*2]   = __halves2half2(__float2half(v.x - __half2float(h0)),
                                          __float2half(v.y - __half2float(h1)));
    ((__half2*)l)[i*2+1] = __halves2half2(__float2half(v.z - __half2float(h2)),
                                          __float2half(v.w - __half2float(h3)));
}

// ---------------- transpose + convert ----------------
__global__ void trconv_k(const float* __restrict__ W, __half* __restrict__ Th,
                         int K, int N, int Npad)
{
    __shared__ float t[32][33];
    int kb = blockIdx.y * 32, nb = blockIdx.x * 32;
    int x = threadIdx.x & 31, y = threadIdx.x >> 5;
    #pragma unroll
    for (int i = y; i < 32; i += 8) {
        int kk = kb + i, nn = nb + x;
        t[i][x] = (kk < K && nn < N) ? W[(size_t)kk * N + nn] : 0.f;
    }
    __syncthreads();
    #pragma unroll
    for (int i = y; i < 32; i += 8) {
        int nn = nb + i, kk = kb + x;
        if (nn < Npad && kk < K)
            Th[(size_t)nn * K + kk] = __float2half(t[x][i]);
    }
}

// ---------------- conv: 4 tokens x 4 channels per thread; fp16 x out, fp32 BC out ----------------
#define NCG (CONV_DIM/4)   // 544 channel groups
__global__ void conv_k(const float* __restrict__ conv_w, const float* __restrict__ conv_b)
{
    int idx = blockIdx.x * blockDim.x + threadIdx.x;
    if (idx >= (MTOK/4) * NCG) return;
    int cg = idx % NCG;
    int tg = idx / NCG;
    int g0 = tg * 4;           // first global token
    int t0 = g0 % LL;          // position in sequence
    int c  = cg * 4;

    float4 w0 = ((const float4*)conv_w)[c+0];
    float4 w1 = ((const float4*)conv_w)[c+1];
    float4 w2 = ((const float4*)conv_w)[c+2];
    float4 w3 = ((const float4*)conv_w)[c+3];
    float4 bias4 = ((const float4*)conv_b)[cg];

    float4 zv[7];
    const float* base = g_zx + (size_t)g0 * DPROJ + DIN + c;
    #pragma unroll
    for (int k = 0; k < 7; k++) {
        int toff = k - 3;
        if (t0 + toff >= 0)
            zv[k] = *(const float4*)(base + (long long)toff * DPROJ);
        else
            zv[k] = make_float4(0.f, 0.f, 0.f, 0.f);
    }

    #pragma unroll
    for (int j = 0; j < 4; j++) {
        float a0 = bias4.x, a1 = bias4.y, a2 = bias4.z, a3 = bias4.w;
        #pragma unroll
        for (int k = 0; k < 4; k++) {
            float4 zvv = zv[j + k];
            float wk0 = (k==0)?w0.x:(k==1)?w0.y:(k==2)?w0.z:w0.w;
            float wk1 = (k==0)?w1.x:(k==1)?w1.y:(k==2)?w1.z:w1.w;
            float wk2 = (k==0)?w2.x:(k==1)?w2.y:(k==2)?w2.z:w2.w;
            float wk3 = (k==0)?w3.x:(k==1)?w3.y:(k==2)?w3.z:w3.w;
            a0 = fmaf(zvv.x, wk0, a0);
            a1 = fmaf(zvv.y, wk1, a1);
            a2 = fmaf(zvv.z, wk2, a2);
            a3 = fmaf(zvv.w, wk3, a3);
        }
        a0 = a0 / (1.f + expf(-a0));
        a1 = a1 / (1.f + expf(-a1));
        a2 = a2 / (1.f + expf(-a2));
        a3 = a3 / (1.f + expf(-a3));
        int tok = g0 + j;
        if (cg < DIN/4) {
            __half2* dst = (__half2*)(g_xsc + (size_t)tok * DIN + c);
            dst[0] = __halves2half2(__float2half(a0), __float2half(a1));
            dst[1] = __halves2half2(__float2half(a2), __float2half(a3));
        } else {
            *(float4*)(g_bc + (size_t)tok * (2*DS) + (cg - DIN/4) * 4) =
                make_float4(a0, a1, a2, a3);
        }
    }
}

// ---------------- Phase A: per-chunk local scan ----------------
__global__ void scan_local_k(const float* __restrict__ D_param)
{
    int chunk = blockIdx.x;
    int bh = blockIdx.y;
    int b = bh >> 5;
    int h = bh & 31;
    int tid = threadIdx.x;
    int p = tid >> 3;
    int n0 = (tid & 7) * 8;
    float hs[8] = {};
    float Dv = D_param[h];
    float cum = 1.f;

    int tok0 = b * LL + chunk * CL;

    float dA_c = g_dA[tok0*NHH + h];
    float dt_c = g_dt[tok0*NHH + h];
    float xp_c = __half2float(g_xsc[(size_t)tok0 * DIN + h*HD + p]);
    const float* bcrow = g_bc + (size_t)tok0 * (2*DS);
    float4 B1c = *(const float4*)(bcrow + n0);
    float4 B2c = *(const float4*)(bcrow + n0 + 4);
    float4 C1c = *(const float4*)(bcrow + DS + n0);
    float4 C2c = *(const float4*)(bcrow + DS + n0 + 4);

    for (int t = 0; t < CL; t++) {
        float dA_n = 0.f, dt_n = 0.f, xp_n = 0.f;
        float4 B1n = {}, B2n = {}, C1n = {}, C2n = {};
        const float* bn = bcrow + 2*DS;
        if (t + 1 < CL) {
            int tokn = tok0 + t + 1;
            dA_n = g_dA[tokn*NHH + h];
            dt_n = g_dt[tokn*NHH + h];
            xp_n = __half2float(g_xsc[(size_t)tokn * DIN + h*HD + p]);
            B1n = *(const float4*)(bn + n0);
            B2n = *(const float4*)(bn + n0 + 4);
            C1n = *(const float4*)(bn + DS + n0);
            C2n = *(const float4*)(bn + DS + n0 + 4);
        }

        cum *= dA_c;
        float dtx = dt_c * xp_c;
        float Bv[8] = {B1c.x,B1c.y,B1c.z,B1c.w,B2c.x,B2c.y,B2c.z,B2c.w};
        float Cv[8] = {C1c.x,C1c.y,C1c.z,C1c.w,C2c.x,C2c.y,C2c.z,C2c.w};
        float part = 0.f;
        #pragma unroll
        for (int i = 0; i < 8; i++) {
            hs[i] = fmaf(dA_c, hs[i], dtx * Bv[i]);
            part  = fmaf(hs[i], Cv[i], part);
        }
        part += __shfl_down_sync(0xffffffffu, part, 4);
        part += __shfl_down_sync(0xffffffffu, part, 2);
        part += __shfl_down_sync(0xffffffffu, part, 1);
        int tok = tok0 + t;
        if ((tid & 7) == 0)
            g_y[(size_t)tok * DIN + h*HD + p] = __float2half(part + Dv * xp_c);
        if (tid == 0)
            g_cumdA[tok*NHH + h] = cum;

        dA_c = dA_n; dt_c = dt_n; xp_c = xp_n;
        B1c = B1n; B2c = B2n; C1c = C1n; C2c = C2n;
        bcrow = bn;
    }

    float* Sp = g_S + ((size_t)bh * NCH + chunk) * (HD*DS) + p * DS + n0;
    #pragma unroll
    for (int i = 0; i < 8; i++) Sp[i] = hs[i];
}

// ---------------- Phase B: combine ----------------
__global__ void scan_combine_k()
{
    int bh = blockIdx.x;
    int b = bh >> 5;
    int h = bh & 31;
    int tid = threadIdx.x;
    int p = tid >> 3;
    int n0 = (tid & 7) * 8;
    float H[8] = {};

    for (int c = 0; c < NCH; c++) {
        float* Hp = g_Hi + ((size_t)bh * NCH + c) * (HD*DS) + p * DS + n0;
        #pragma unroll
        for (int i = 0; i < 8; i++) Hp[i] = H[i];
        if (c + 1 < NCH) {
            int lastTok = b * LL + c * CL + (CL - 1);
            float Pc = g_cumdA[lastTok*NHH + h];
            const float* Sp = g_S + ((size_t)bh * NCH + c) * (HD*DS) + p * DS + n0;
            #pragma unroll
            for (int i = 0; i < 8; i++) H[i] = fmaf(Pc, H[i], Sp[i]);
        }
    }
}

// ---------------- Phase C: cross-chunk correction ----------------
__global__ void scan_correct_k()
{
    int chunk = blockIdx.x + 1;
    int bh = blockIdx.y;
    int b = bh >> 5;
    int h = bh & 31;
    int tid = threadIdx.x;
    int p = tid >> 3;
    int n0 = (tid & 7) * 8;

    float H[8];
    const float* Hp = g_Hi + ((size_t)bh * NCH + chunk) * (HD*DS) + p * DS + n0;
    #pragma unroll
    for (int i = 0; i < 8; i++) H[i] = Hp[i];

    int tok0 = b * LL + chunk * CL;
    const float* bcrow = g_bc + (size_t)tok0 * (2*DS);

    #pragma unroll 2
    for (int t = 0; t < CL; t++) {
        int tok = tok0 + t;
        float4 C1 = *(const float4*)(bcrow + DS + n0);
        float4 C2 = *(const float4*)(bcrow + DS + n0 + 4);
        float cum = g_cumdA[tok*NHH + h];
        float Cv[8] = {C1.x,C1.y,C1.z,C1.w,C2.x,C2.y,C2.z,C2.w};
        float part = 0.f;
        #pragma unroll
        for (int i = 0; i < 8; i++) part = fmaf(H[i], Cv[i], part);
        part += __shfl_down_sync(0xffffffffu, part, 4);
        part += __shfl_down_sync(0xffffffffu, part, 2);
        part += __shfl_down_sync(0xffffffffu, part, 1);
        if ((tid & 7) == 0) {
            __half* yp = g_y + (size_t)tok * DIN + h*HD + p;
            *yp = __float2half(__half2float(*yp) + cum * part);
        }
        bcrow += 2*DS;
    }
}

// ---------------- gated RMSNorm -> fp16 ----------------
__global__ void __launch_bounds__(512) gatenorm_k(const float* __restrict__ norm_w)
{
    int tok = blockIdx.x;
    int tid = threadIdx.x;
    __shared__ float red[16];

    __half2 ya = ((const __half2*)(g_y + (size_t)tok * DIN))[tid*2];
    __half2 yb = ((const __half2*)(g_y + (size_t)tok * DIN))[tid*2+1];
    __half2 z01 = ((const __half2*)(g_sz + (size_t)tok * DIN))[tid*2];
    __half2 z23 = ((const __half2*)(g_sz + (size_t)tok * DIN))[tid*2+1];
    float v0 = __half2float(ya.x) * __half2float(z01.x);
    float v1 = __half2float(ya.y) * __half2float(z01.y);
    float v2 = __half2float(yb.x) * __half2float(z23.x);
    float v3 = __half2float(yb.y) * __half2float(z23.y);
    float ss = v0*v0 + v1*v1 + v2*v2 + v3*v3;
    #pragma unroll
    for (int o = 16; o > 0; o >>= 1) ss += __shfl_xor_sync(0xffffffffu, ss, o);
    if ((tid & 31) == 0) red[tid >> 5] = ss;
    __syncthreads();
    if (tid < 32) {
        float s = (tid < 16) ? red[tid] : 0.f;
        #pragma unroll
        for (int o = 8; o > 0; o >>= 1) s += __shfl_xor_sync(0xffffffffu, s, o);
        if (tid == 0) red[0] = s;
    }
    __syncthreads();
    float scale = rsqrtf(red[0] / DIN + EPSV);
    float4 w4 = ((const float4*)norm_w)[tid];
    ((__half2*)(g_yn_h + (size_t)tok * DIN))[tid*2] =
        __halves2half2(__float2half(v0 * scale * w4.x), __float2half(v1 * scale * w4.y));
    ((__half2*)(g_yn_h + (size_t)tok * DIN))[tid*2+1] =
        __halves2half2(__float2half(v2 * scale * w4.z), __float2half(v3 * scale * w4.w));
}

// ---------------- plain RMSNorm -> fp16 ----------------
__global__ void __launch_bounds__(512) rmsnorm_k(const float* __restrict__ x,
                                                 const float* __restrict__ w)
{
    int tok = blockIdx.x;
    int tid = threadIdx.x;
    __shared__ float red[16];

    float2 v = ((const float2*)(x + (size_t)tok * DM))[tid];
    float ss = v.x*v.x + v.y*v.y;
    #pragma unroll
    for (int o = 16; o > 0; o >>= 1) ss += __shfl_xor_sync(0xffffffffu, ss, o);
    if ((tid & 31) == 0) red[tid >> 5] = ss;
    __syncthreads();
    if (tid < 32) {
        float s = (tid < 16) ? red[tid] : 0.f;
        #pragma unroll
        for (int o = 8; o > 0; o >>= 1) s += __shfl_xor_sync(0xffffffffu, s, o);
        if (tid == 0) red[0] = s;
    }
    __syncthreads();
    float scale = rsqrtf(red[0] / DM + EPSV);
    float2 w2 = ((const float2*)w)[tid];
    ((__half2*)(g_hn_h + (size_t)tok * DM))[tid] =
        __halves2half2(__float2half(v.x * scale * w2.x),
                       __float2half(v.y * scale * w2.y));
}

// ---------------- launch ----------------
extern "C" void kernel_launch(void* const* d_in, const int* in_sizes, int n_in,
                              void* d_out, int out_size)
{
    const float* x       = (const float*)d_in[0];
    const float* W_in    = (const float*)d_in[1];
    const float* conv_w  = (const float*)d_in[2];
    const float* conv_b  = (const float*)d_in[3];
    const float* dt_bias = (const float*)d_in[4];
    const float* A_log   = (const float*)d_in[5];
    const float* D_param = (const float*)d_in[6];
    const float* norm_w  = (const float*)d_in[7];
    const float* W_out   = (const float*)d_in[8];
    const float* rms_w   = (const float*)d_in[9];
    const float* mlp_w1  = (const float*)d_in[10];
    const float* mlp_b1  = (const float*)d_in[11];
    const float* mlp_w2  = (const float*)d_in[12];
    const float* mlp_b2  = (const float*)d_in[13];
    float* out           = (float*)d_out;
    (void)in_sizes; (void)n_in; (void)out_size;

    float *p_zx, *p_h;
    __half *p_sz, *p_xs_h, *p_xs_l, *p_yn_h, *p_hn_h, *p_act_h;
    __half *p_win, *p_wout, *p_w1, *p_w2;
    cudaGetSymbolAddress((void**)&p_zx, g_zx);
    cudaGetSymbolAddress((void**)&p_h, g_h);
    cudaGetSymbolAddress((void**)&p_sz, g_sz);
    cudaGetSymbolAddress((void**)&p_xs_h, g_xs_h);   cudaGetSymbolAddress((void**)&p_xs_l, g_xs_l);
    cudaGetSymbolAddress((void**)&p_yn_h, g_yn_h);
    cudaGetSymbolAddress((void**)&p_hn_h, g_hn_h);
    cudaGetSymbolAddress((void**)&p_act_h, g_act_h);
    cudaGetSymbolAddress((void**)&p_win, g_win);
    cudaGetSymbolAddress((void**)&p_wout, g_wout);
    cudaGetSymbolAddress((void**)&p_w1, g_w1);
    cudaGetSymbolAddress((void**)&p_w2, g_w2);

    cudaFuncSetAttribute(gemm_mma<0,0,0,3,2>, cudaFuncAttributeMaxDynamicSharedMemorySize, GEMM_SMEM);
    cudaFuncSetAttribute(gemm_mma<0,0,0,0,1>, cudaFuncAttributeMaxDynamicSharedMemorySize, GEMM_SMEM);
    cudaFuncSetAttribute(gemm_mma<0,1,0,2,1>, cudaFuncAttributeMaxDynamicSharedMemorySize, GEMM_SMEM);
    cudaFuncSetAttribute(gemm_mma<0,0,1,0,1>, cudaFuncAttributeMaxDynamicSharedMemorySize, GEMM_SMEM);
    cudaFuncSetAttribute(gemm_mma<1,1,0,2,1>, cudaFuncAttributeMaxDynamicSharedMemorySize, GEMM_SMEM);
    cudaFuncSetAttribute(gemm_mma<1,0,1,0,1>, cudaFuncAttributeMaxDynamicSharedMemorySize, GEMM_SMEM);

    static cudaStream_t s1 = nullptr;
    static cudaEvent_t ev0 = nullptr, evA = nullptr, evW = nullptr, evJ = nullptr;
    if (!s1) {
        cudaStreamCreateWithFlags(&s1, cudaStreamNonBlocking);
        cudaEventCreateWithFlags(&ev0, cudaEventDisableTiming);
        cudaEventCreateWithFlags(&evA, cudaEventDisableTiming);
        cudaEventCreateWithFlags(&evW, cudaEventDisableTiming);
        cudaEventCreateWithFlags(&evJ, cudaEventDisableTiming);
    }

    dim3 blk(256);

    cudaEventRecord(ev0, 0);
    cudaStreamWaitEvent(s1, ev0, 0);

    // main: activation split
    split_k<<<(MTOK*DM/4 + 255)/256, blk>>>(x, p_xs_h, p_xs_l, MTOK*DM/4);
    cudaEventRecord(evA, 0);

    // side: weight transposes, then z-GEMM
    trconv_k<<<dim3(DPROJ_PAD/32, DM/32), blk, 0, s1>>>(W_in, p_win, DM, DPROJ, DPROJ_PAD);
    cudaEventRecord(evW, s1);
    trconv_k<<<dim3(DM/32, DIN/32),  blk, 0, s1>>>(W_out,  p_wout, DIN,  DM,   DM);
    trconv_k<<<dim3(MLPI/32, DM/32), blk, 0, s1>>>(mlp_w1, p_w1,   DM,   MLPI, MLPI);
    trconv_k<<<dim3(DM/32, MLPI/32), blk, 0, s1>>>(mlp_w2, p_w2,   MLPI, DM,   DM);
    cudaStreamWaitEvent(s1, evA, 0);
    gemm_mma<0,1,0,2,1><<<dim3(DIN/NT, MTOK/MT), 512, GEMM_SMEM, s1>>>(
        p_xs_h, nullptr, p_win, nullptr, nullptr,
        nullptr, p_sz, MTOK, DIN, DM, DIN);
    cudaEventRecord(evJ, s1);

    // main: in-proj
    cudaStreamWaitEvent(0, evW, 0);
    // B/C/dt cols: 2-term; B/C fp32 -> zx cols 4096..4223 (ldc DPROJ), dt/dA in epilogue
    gemm_mma<0,0,0,3,2><<<dim3((NBCDT+NT-1)/NT, MTOK/MT), 512, GEMM_SMEM>>>(
        p_xs_h, p_xs_l, p_win + (size_t)(2*DIN) * DM, dt_bias, A_log,
        p_zx + 2*DIN, nullptr, MTOK, NBCDT, DM, DPROJ);
    // x cols: 1-term, fp32 -> zx cols 2048..4095
    gemm_mma<0,0,0,0,1><<<dim3(DIN/NT, MTOK/MT), 512, GEMM_SMEM>>>(
        p_xs_h, nullptr, p_win + (size_t)DIN * DM, nullptr, nullptr,
        p_zx + DIN, nullptr, MTOK, DIN, DM, DPROJ);

    // conv + silu, chunked scan (dt_k eliminated — fused into GEMM epilogue)
    conv_k<<<((MTOK/4)*NCG + 255)/256, blk>>>(conv_w, conv_b);
    scan_local_k<<<dim3(NCH, BB*NHH), 512>>>(D_param);
    scan_combine_k<<<BB*NHH, 512>>>();
    scan_correct_k<<<dim3(NCH-1, BB*NHH), 512>>>();

    cudaStreamWaitEvent(0, evJ, 0);

    gatenorm_k<<<MTOK, 512>>>(norm_w);
    gemm_mma<0,0,1,0,1><<<dim3(DM/NT, MTOK/MT), 512, GEMM_SMEM>>>(
        p_yn_h, nullptr, p_wout, nullptr, x, p_h, nullptr,
        MTOK, DM, DIN, DM);
    rmsnorm_k<<<MTOK, 512>>>(p_h, rms_w);
    gemm_mma<1,1,0,2,1><<<dim3(MLPI/NT, MTOK/MT), 512, GEMM_SMEM>>>(
        p_hn_h, nullptr, p_w1, mlp_b1, nullptr, nullptr, p_act_h,
        MTOK, MLPI, DM, MLPI);
    gemm_mma<1,0,1,0,1><<<dim3(DM/NT, MTOK/MT), 512, GEMM_SMEM>>>(
        p_act_h, nullptr, p_w2, mlp_b2, p_h, out, nullptr,
        MTOK, DM, MLPI, DM);
}